// round 15
// baseline (speedup 1.0000x reference)
#include <cuda_runtime.h>
#include <stdint.h>

// Problem constants
#define BB 32
#define NN 1024
#define DD 768
#define D4 (DD/4)          // 192 float4 per row
#define KMASK 768          // masked tokens per row
#define NUNM  256          // unmasked tokens per row

#define TOKB 4             // tokens per scatter block
#define SCAT_THREADS 256
#define SCAT_ITERS 3       // 4 tokens * 192 f4 = 768 = 3 * 256

// Output layout (float32 concat of the 5 reference outputs, flattened in order)
#define OFF_WITHMASK 0ull
#define OFF_UNMP   ((unsigned long long)BB*NN*DD)                       // 25165824
#define OFF_BOOL   (OFF_UNMP + (unsigned long long)BB*NUNM*DD)          // 31457280
#define OFF_MIDX   (OFF_BOOL + (unsigned long long)BB*NN*DD)            // 56623104
#define OFF_UIDX   (OFF_MIDX + (unsigned long long)BB*KMASK)            // 56647680

// Scratch: per-token info. -1 => masked; else rank among unmasked (0..255)
__device__ int g_info[BB * NN];

// ---------------------------------------------------------------------------
// Kernel 1: O(N) bucket-rank argsort + fused finalize.
// One 1024-thread block per batch row. Uniform noise in [0,1): bucket
// c = min(1023, int(v*1024)) is order-preserving; rank = bucket offset
// (block scan of counts) + exact within-bucket count on the full key
// (float_bits<<10 | index) -> identical stable-argsort semantics to the
// verified bitonic, with ~4 barriers instead of 15 and no 55-stage chain.
// ---------------------------------------------------------------------------
__global__ __launch_bounds__(1024, 1)
void mask_sort_kernel(const float* __restrict__ noise, float* __restrict__ out)
{
    __shared__ int s_cnt[NN];                    // bucket counts
    __shared__ int s_off[NN + 1];                // exclusive offsets (+guard)
    __shared__ unsigned long long s_keys[NN];    // keys grouped by bucket
    __shared__ int s_mask[NN];                   // bool_mask by sorted position
    __shared__ int warp_sums[32];

    const int b = blockIdx.x;
    const int t = threadIdx.x;
    const int lane = t & 31;
    const int warp = t >> 5;

    const float v = noise[b * NN + t];
    const unsigned long long key =
        ((unsigned long long)__float_as_uint(v) << 10) | (unsigned)t;
    int c = (int)(v * 1024.0f);
    c = min(c, NN - 1);

    s_cnt[t] = 0;
    __syncthreads();
    const int a = atomicAdd(&s_cnt[c], 1);       // arrival slot within bucket
    __syncthreads();

    // Block-wide exclusive scan of the 1024 bucket counts.
    const int cnt = s_cnt[t];
    int incl = cnt;
    #pragma unroll
    for (int d = 1; d < 32; d <<= 1) {
        int x = __shfl_up_sync(0xFFFFFFFFu, incl, d);
        if (lane >= d) incl += x;
    }
    if (lane == 31) warp_sums[warp] = incl;
    __syncthreads();
    if (warp == 0) {
        int ws = warp_sums[lane];
        #pragma unroll
        for (int d = 1; d < 32; d <<= 1) {
            int x = __shfl_up_sync(0xFFFFFFFFu, ws, d);
            if (lane >= d) ws += x;
        }
        warp_sums[lane] = ws;
    }
    __syncthreads();
    const int warp_off = (warp == 0) ? 0 : warp_sums[warp - 1];
    s_off[t] = warp_off + incl - cnt;            // exclusive offset of bucket t
    if (t == 0) s_off[NN] = NN;
    __syncthreads();

    // Place key into its bucket region; then exact rank within bucket.
    s_keys[s_off[c] + a] = key;
    __syncthreads();
    const int base = s_off[c];
    const int n    = s_off[c + 1] - base;
    int r = base;
    for (int i = 0; i < n; ++i)
        r += (s_keys[base + i] < key) ? 1 : 0;

    // Element with original index t has sorted position r:
    // bool_mask[r] = (perm[r] < KMASK) = (t < KMASK).
    s_mask[r] = (t < KMASK) ? 1 : 0;
    __syncthreads();

    const int m = s_mask[t];                     // bool_mask at position t

    // Exclusive prefix sum of m (ballot + warp sums) — verified epilogue.
    unsigned ballot = __ballot_sync(0xFFFFFFFFu, m);
    int before_in_warp = __popc(ballot & ((1u << lane) - 1u));
    if (lane == 0) warp_sums[warp] = __popc(ballot);
    __syncthreads();
    int warp_before = 0;
    #pragma unroll
    for (int w = 0; w < 32; ++w)
        warp_before += (w < warp) ? warp_sums[w] : 0;
    int t_before = warp_before + before_in_warp;

    // order = stable argsort(bool_mask): False positions first, then True.
    float* masked_out = out + OFF_MIDX;
    float* unm_out    = out + OFF_UIDX;
    if (m) {
        masked_out[b * KMASK + t_before] = (float)t;
        g_info[b * NN + t] = -1;
    } else {
        int rr = t - t_before;
        unm_out[b * NUNM + rr] = (float)t;
        g_info[b * NN + t] = rr;
    }

    cudaTriggerProgrammaticLaunchCompletion();
}

// ---------------------------------------------------------------------------
// Kernel 2: scatter (R13-verified, best-measured variant): 4 tokens per
// 256-thread block, MLP-batched loads then stores, plain caching ops.
// ---------------------------------------------------------------------------
__global__ __launch_bounds__(SCAT_THREADS, 8)
void mask_scatter_kernel(const float* __restrict__ patch,
                         const float* __restrict__ mask_emb,
                         float* __restrict__ out)
{
    __shared__ float4 s_me[D4];
    __shared__ int s_info[TOKB];

    const int tok0 = blockIdx.x * TOKB;          // 4 | 1024 -> single batch
    const int b    = tok0 >> 10;
    const int t    = threadIdx.x;

    // mask_emb is sort-independent: load before the grid dependency resolves.
    if (t < D4)
        s_me[t] = __ldg(reinterpret_cast<const float4*>(mask_emb) + t);

    cudaGridDependencySynchronize();

    if (t < TOKB) s_info[t] = __ldg(&g_info[tok0 + t]);
    __syncthreads();

    const float4* patch4 = reinterpret_cast<const float4*>(patch);
    float4* wm_base = reinterpret_cast<float4*>(out + OFF_WITHMASK);
    float4* be_base = reinterpret_cast<float4*>(out + OFF_BOOL);
    float4* up_base = reinterpret_cast<float4*>(out + OFF_UNMP);

    const size_t base = (size_t)tok0 * D4;       // block-contiguous region

    int   infos[SCAT_ITERS];
    int   lanes[SCAT_ITERS];
    size_t gidx[SCAT_ITERS];
    float4 pch[SCAT_ITERS];

    #pragma unroll
    for (int it = 0; it < SCAT_ITERS; ++it) {
        const int e  = it * SCAT_THREADS + t;    // 0..767
        const int tl = e / D4;                   // token 0..3
        lanes[it] = e - tl * D4;
        infos[it] = s_info[tl];
        gidx[it]  = base + e;
        if (infos[it] >= 0)
            pch[it] = patch4[gidx[it]];
    }

    #pragma unroll
    for (int it = 0; it < SCAT_ITERS; ++it) {
        const int info = infos[it];
        const float bv = (info < 0) ? 1.0f : 0.0f;
        be_base[gidx[it]] = make_float4(bv, bv, bv, bv);

        if (info < 0) {
            wm_base[gidx[it]] = s_me[lanes[it]];
        } else {
            wm_base[gidx[it]] = pch[it];
            up_base[((size_t)b * NUNM + info) * D4 + lanes[it]] = pch[it];
        }
    }
}

extern "C" void kernel_launch(void* const* d_in, const int* in_sizes, int n_in,
                              void* d_out, int out_size)
{
    const float* patch    = (const float*)d_in[0];  // (B, N, D) f32
    const float* noise    = (const float*)d_in[1];  // (B, N)    f32
    const float* mask_emb = (const float*)d_in[2];  // (D,)      f32
    float* out = (float*)d_out;

    // Primary: sort (PDL completion at its end).
    mask_sort_kernel<<<BB, 1024>>>(noise, out);

    // Secondary: PDL — launch/prologue overlaps the sort; g_info reads are
    // ordered by cudaGridDependencySynchronize.
    cudaLaunchAttribute attrs[1];
    attrs[0].id = cudaLaunchAttributeProgrammaticStreamSerialization;
    attrs[0].val.programmaticStreamSerializationAllowed = 1;

    cudaLaunchConfig_t cfg = {};
    cfg.gridDim  = dim3(BB * NN / TOKB, 1, 1);
    cfg.blockDim = dim3(SCAT_THREADS, 1, 1);
    cfg.dynamicSmemBytes = 0;
    cfg.stream = 0;
    cfg.attrs = attrs;
    cfg.numAttrs = 1;

    cudaLaunchKernelEx(&cfg, mask_scatter_kernel, patch, mask_emb, out);
}

// round 16
// speedup vs baseline: 1.1817x; 1.1817x over previous
#include <cuda_runtime.h>
#include <stdint.h>

// Problem constants
#define BB 32
#define NN 1024
#define DD 768
#define D4 (DD/4)          // 192 float4 per row
#define KMASK 768          // masked tokens per row
#define NUNM  256          // unmasked tokens per row

// Output layout (float32 concat of the 5 reference outputs, flattened in order)
#define OFF_WITHMASK 0ull
#define OFF_UNMP   ((unsigned long long)BB*NN*DD)                       // 25165824
#define OFF_BOOL   (OFF_UNMP + (unsigned long long)BB*NUNM*DD)          // 31457280
#define OFF_MIDX   (OFF_BOOL + (unsigned long long)BB*NN*DD)            // 56623104
#define OFF_UIDX   (OFF_MIDX + (unsigned long long)BB*KMASK)            // 56647680

// Scratch: per-token info. -1 => masked; else rank among unmasked (0..255)
__device__ int g_info[BB * NN];

// ---------------------------------------------------------------------------
// Kernel 1: O(N) bucket-rank argsort + fused finalize (verified R15).
// One 1024-thread block per batch row. Uniform noise in [0,1): bucket
// c = min(1023, int(v*1024)) is order-preserving; rank = bucket offset
// (block scan of counts) + exact within-bucket count on the full key
// (float_bits<<10 | index) -> identical stable-argsort semantics to the
// bitonic, with ~4 barriers and no 55-stage dependent chain.
// PDL completion triggered at the END (R6 semantics).
// ---------------------------------------------------------------------------
__global__ __launch_bounds__(1024, 1)
void mask_sort_kernel(const float* __restrict__ noise, float* __restrict__ out)
{
    __shared__ int s_cnt[NN];                    // bucket counts
    __shared__ int s_off[NN + 1];                // exclusive offsets (+guard)
    __shared__ unsigned long long s_keys[NN];    // keys grouped by bucket
    __shared__ int s_mask[NN];                   // bool_mask by sorted position
    __shared__ int warp_sums[32];

    const int b = blockIdx.x;
    const int t = threadIdx.x;
    const int lane = t & 31;
    const int warp = t >> 5;

    const float v = noise[b * NN + t];
    const unsigned long long key =
        ((unsigned long long)__float_as_uint(v) << 10) | (unsigned)t;
    int c = (int)(v * 1024.0f);
    c = min(c, NN - 1);

    s_cnt[t] = 0;
    __syncthreads();
    const int a = atomicAdd(&s_cnt[c], 1);       // arrival slot within bucket
    __syncthreads();

    // Block-wide exclusive scan of the 1024 bucket counts.
    const int cnt = s_cnt[t];
    int incl = cnt;
    #pragma unroll
    for (int d = 1; d < 32; d <<= 1) {
        int x = __shfl_up_sync(0xFFFFFFFFu, incl, d);
        if (lane >= d) incl += x;
    }
    if (lane == 31) warp_sums[warp] = incl;
    __syncthreads();
    if (warp == 0) {
        int ws = warp_sums[lane];
        #pragma unroll
        for (int d = 1; d < 32; d <<= 1) {
            int x = __shfl_up_sync(0xFFFFFFFFu, ws, d);
            if (lane >= d) ws += x;
        }
        warp_sums[lane] = ws;
    }
    __syncthreads();
    const int warp_off = (warp == 0) ? 0 : warp_sums[warp - 1];
    s_off[t] = warp_off + incl - cnt;            // exclusive offset of bucket t
    if (t == 0) s_off[NN] = NN;
    __syncthreads();

    // Place key into its bucket region; then exact rank within bucket.
    s_keys[s_off[c] + a] = key;
    __syncthreads();
    const int base = s_off[c];
    const int n    = s_off[c + 1] - base;
    int r = base;
    for (int i = 0; i < n; ++i)
        r += (s_keys[base + i] < key) ? 1 : 0;

    // Element with original index t has sorted position r:
    // bool_mask[r] = (perm[r] < KMASK) = (t < KMASK).
    s_mask[r] = (t < KMASK) ? 1 : 0;
    __syncthreads();

    const int m = s_mask[t];                     // bool_mask at position t

    // Exclusive prefix sum of m (ballot + warp sums) — verified epilogue.
    unsigned ballot = __ballot_sync(0xFFFFFFFFu, m);
    int before_in_warp = __popc(ballot & ((1u << lane) - 1u));
    if (lane == 0) warp_sums[warp] = __popc(ballot);
    __syncthreads();
    int warp_before = 0;
    #pragma unroll
    for (int w = 0; w < 32; ++w)
        warp_before += (w < warp) ? warp_sums[w] : 0;
    int t_before = warp_before + before_in_warp;

    // order = stable argsort(bool_mask): False positions first, then True.
    float* masked_out = out + OFF_MIDX;
    float* unm_out    = out + OFF_UIDX;
    if (m) {
        masked_out[b * KMASK + t_before] = (float)t;
        g_info[b * NN + t] = -1;
    } else {
        int rr = t - t_before;
        unm_out[b * NUNM + rr] = (float)t;
        g_info[b * NN + t] = rr;
    }

    cudaTriggerProgrammaticLaunchCompletion();
}

// ---------------------------------------------------------------------------
// Kernel 2: scatter — exact R6 configuration (best verified total, 51.2us).
// One token per block (32768 x 192 thr, 10 CTAs/SM). mask_emb loaded before
// the grid dependency resolves; streaming hints on the write-once outputs.
// ---------------------------------------------------------------------------
__global__ __launch_bounds__(192, 10)
void mask_scatter_kernel(const float* __restrict__ patch,
                         const float* __restrict__ mask_emb,
                         float* __restrict__ out)
{
    const int tok = blockIdx.x;          // b*N + j
    const int b   = tok >> 10;
    const int t   = threadIdx.x;         // float4 lane 0..191

    // Independent of the sort result — overlap with producer via PDL.
    const float4 me = __ldg(reinterpret_cast<const float4*>(mask_emb) + t);

    cudaGridDependencySynchronize();

    const int info = __ldg(&g_info[tok]);

    float4* wm = reinterpret_cast<float4*>(out + OFF_WITHMASK) + (size_t)tok * D4;
    float4* be = reinterpret_cast<float4*>(out + OFF_BOOL)     + (size_t)tok * D4;

    const float bv = (info < 0) ? 1.0f : 0.0f;
    __stcs(be + t, make_float4(bv, bv, bv, bv));

    if (info < 0) {
        __stcs(wm + t, me);
    } else {
        float4 pch = __ldcs(reinterpret_cast<const float4*>(patch) + (size_t)tok * D4 + t);
        __stcs(wm + t, pch);
        float4* up = reinterpret_cast<float4*>(out + OFF_UNMP)
                   + ((size_t)b * NUNM + info) * D4;
        __stcs(up + t, pch);
    }
}

extern "C" void kernel_launch(void* const* d_in, const int* in_sizes, int n_in,
                              void* d_out, int out_size)
{
    const float* patch    = (const float*)d_in[0];  // (B, N, D) f32
    const float* noise    = (const float*)d_in[1];  // (B, N)    f32
    const float* mask_emb = (const float*)d_in[2];  // (D,)      f32
    float* out = (float*)d_out;

    // Primary: sort (PDL completion at its end).
    mask_sort_kernel<<<BB, 1024>>>(noise, out);

    // Secondary: PDL — launch/prologue overlaps the sort; g_info reads are
    // ordered by cudaGridDependencySynchronize.
    cudaLaunchAttribute attrs[1];
    attrs[0].id = cudaLaunchAttributeProgrammaticStreamSerialization;
    attrs[0].val.programmaticStreamSerializationAllowed = 1;

    cudaLaunchConfig_t cfg = {};
    cfg.gridDim  = dim3(BB * NN, 1, 1);
    cfg.blockDim = dim3(192, 1, 1);
    cfg.dynamicSmemBytes = 0;
    cfg.stream = 0;
    cfg.attrs = attrs;
    cfg.numAttrs = 1;

    cudaLaunchKernelEx(&cfg, mask_scatter_kernel, patch, mask_emb, out);
}